// round 2
// baseline (speedup 1.0000x reference)
#include <cuda_runtime.h>
#include <math.h>

#define T_TOK 16384
#define C_DIM 2048
#define E_NUM 64

__device__ float g_ctx[4 * C_DIM];      // (4, 2048)  context projection
__device__ float g_imp[E_NUM];          // sum of probs per expert
__device__ float g_load[E_NUM];         // top-k pick counts per expert

// ---------------------------------------------------------------------------
// Kernel 1: ctx[b][c] = sum_k rc[b][k] * ctx_w[c][k]   (warp per column c)
// Also zeroes the global accumulators (runs first every replay).
// ---------------------------------------------------------------------------
__global__ void __launch_bounds__(256) ctx_kernel(const float* __restrict__ rc,
                                                  const float* __restrict__ ctx_w)
{
    if (blockIdx.x == 0 && threadIdx.x < 2 * E_NUM) {
        if (threadIdx.x < E_NUM) g_imp[threadIdx.x] = 0.f;
        else                     g_load[threadIdx.x - E_NUM] = 0.f;
    }
    int warp  = blockIdx.x * (blockDim.x >> 5) + (threadIdx.x >> 5);
    int lane  = threadIdx.x & 31;
    int nwarp = gridDim.x * (blockDim.x >> 5);
    for (int c = warp; c < C_DIM; c += nwarp) {
        const float* w = ctx_w + (size_t)c * C_DIM;
        float a0 = 0.f, a1 = 0.f, a2 = 0.f, a3 = 0.f;
        for (int k = lane; k < C_DIM; k += 32) {
            float wv = w[k];
            a0 = fmaf(rc[k            ], wv, a0);
            a1 = fmaf(rc[C_DIM     + k], wv, a1);
            a2 = fmaf(rc[2 * C_DIM + k], wv, a2);
            a3 = fmaf(rc[3 * C_DIM + k], wv, a3);
        }
        #pragma unroll
        for (int o = 16; o; o >>= 1) {
            a0 += __shfl_down_sync(0xffffffffu, a0, o);
            a1 += __shfl_down_sync(0xffffffffu, a1, o);
            a2 += __shfl_down_sync(0xffffffffu, a2, o);
            a3 += __shfl_down_sync(0xffffffffu, a3, o);
        }
        if (lane == 0) {
            g_ctx[c]             = a0;
            g_ctx[C_DIM + c]     = a1;
            g_ctx[2 * C_DIM + c] = a2;
            g_ctx[3 * C_DIM + c] = a3;
        }
    }
}

// ---------------------------------------------------------------------------
// Kernel 2: main GEMM (logits = (x + ctx) @ gate_w.T) + fused router
// epilogue (top-2, softmax weights, importance/load accumulation).
// The ctx add happens at x-tile load time so rounding matches the reference
// ((x + ctx) rounded to fp32 BEFORE the matmul) exactly.
// Block: 256 threads, BM=128 tokens, all 64 experts, BK=16.
// Thread micro-tile: 4 tokens x 8 experts.
// ---------------------------------------------------------------------------
__global__ void __launch_bounds__(256, 1) router_kernel(const float* __restrict__ x,
                                                        const float* __restrict__ gate_w,
                                                        float* __restrict__ out)
{
    __shared__ float xs[16 * 128];     // xs[k][token]  (k-major)
    __shared__ float gs[16 * 64];      // gs[k][expert]
    __shared__ float sLog[128 * 65];   // padded logits rows
    __shared__ float sImp[E_NUM];
    __shared__ int   sLoad[E_NUM];

    const int tid    = threadIdx.x;
    const int token0 = blockIdx.x * 128;
    const int batch  = token0 >> 12;   // 128 | 4096, so one batch per block

    // loader mapping: tid -> (row lt, k-quad lk)
    const int lt = tid >> 2;          // 0..63
    const int lk = (tid & 3) << 2;    // 0,4,8,12
    const float4* xpA = (const float4*)(x      + (size_t)(token0 + lt)      * C_DIM + lk);
    const float4* xpB = (const float4*)(x      + (size_t)(token0 + lt + 64) * C_DIM + lk);
    const float4* gp  = (const float4*)(gate_w + (size_t)lt                 * C_DIM + lk);
    const float4* cp  = (const float4*)(g_ctx  + (size_t)batch              * C_DIM + lk);

    // compute mapping: tid -> (token base ti, expert base ej)
    const int ti = (tid & 31) << 2;   // 0..124 step 4
    const int ej = (tid >> 5) << 3;   // 0..56  step 8

    float acc[4][8];
    #pragma unroll
    for (int a = 0; a < 4; a++)
        #pragma unroll
        for (int b = 0; b < 8; b++) acc[a][b] = 0.f;

    float4 ra = *xpA, rb = *xpB, rg = *gp, rc = *cp;

    for (int kc = 0; kc < 128; kc++) {
        // store current chunk (transposed to k-major), ctx fused into x
        #pragma unroll
        for (int i = 0; i < 4; i++) {
            float cv = ((const float*)&rc)[i];
            xs[(lk + i) * 128 + lt]      = ((const float*)&ra)[i] + cv;
            xs[(lk + i) * 128 + lt + 64] = ((const float*)&rb)[i] + cv;
            gs[(lk + i) * 64 + lt]       = ((const float*)&rg)[i];
        }
        __syncthreads();
        // prefetch next chunk (LDG overlaps the FMA block below)
        if (kc < 127) {
            ra = xpA[(kc + 1) * 4];
            rb = xpB[(kc + 1) * 4];
            rg = gp [(kc + 1) * 4];
            rc = cp [(kc + 1) * 4];
        }
        #pragma unroll
        for (int kk = 0; kk < 16; kk++) {
            float4 xv = *(const float4*)&xs[kk * 128 + ti];
            float4 g0 = *(const float4*)&gs[kk * 64 + ej];
            float4 g1 = *(const float4*)&gs[kk * 64 + ej + 4];
            float xr[4] = {xv.x, xv.y, xv.z, xv.w};
            float gr[8] = {g0.x, g0.y, g0.z, g0.w, g1.x, g1.y, g1.z, g1.w};
            #pragma unroll
            for (int a = 0; a < 4; a++)
                #pragma unroll
                for (int b = 0; b < 8; b++)
                    acc[a][b] = fmaf(xr[a], gr[b], acc[a][b]);
        }
        __syncthreads();
    }

    // spill logits to smem (padded rows: stride 65 avoids bank conflicts)
    if (tid < E_NUM) { sImp[tid] = 0.f; sLoad[tid] = 0; }
    #pragma unroll
    for (int a = 0; a < 4; a++)
        #pragma unroll
        for (int b = 0; b < 8; b++)
            sLog[(ti + a) * 65 + ej + b] = acc[a][b];
    __syncthreads();

    // -------- fused epilogue: one thread per token --------
    if (tid < 128) {
        const int tok = token0 + tid;
        float* row = &sLog[tid * 65];

        // top-2 with jax tie-break (strict >, lowest index wins ties)
        float v0 = -1e30f, v1 = -1e30f;
        int   i0 = 0, i1 = 0;
        for (int e = 0; e < E_NUM; e++) {
            float l = row[e];
            if (l > v0)      { v1 = v0; i1 = i0; v0 = l; i0 = e; }
            else if (l > v1) { v1 = l; i1 = e; }
        }
        // full softmax (stable at max v0); cache exp in row
        float sum = 0.f;
        for (int e = 0; e < E_NUM; e++) {
            float p = expf(row[e] - v0);
            row[e] = p;
            sum += p;
        }
        float inv = 1.0f / sum;
        // importance accumulation, lane-staggered to avoid same-address atomics
        int lane = tid & 31;
        for (int e = 0; e < E_NUM; e++) {
            int ee = (e + lane) & 63;
            atomicAdd(&sImp[ee], row[ee] * inv);
        }
        atomicAdd(&sLoad[i0], 1);
        atomicAdd(&sLoad[i1], 1);

        // top-2 softmax weights
        float e1 = expf(v1 - v0);
        float w0 = 1.0f / (1.0f + e1);
        out[(size_t)tok * 2 + 0] = (float)i0;
        out[(size_t)tok * 2 + 1] = (float)i1;
        out[2 * T_TOK + (size_t)tok * 2 + 0] = w0;
        out[2 * T_TOK + (size_t)tok * 2 + 1] = e1 * w0;   // = 1 - w0
    }
    __syncthreads();
    if (tid < E_NUM) {
        atomicAdd(&g_imp[tid],  sImp[tid]);
        atomicAdd(&g_load[tid], (float)sLoad[tid]);
    }
}

// ---------------------------------------------------------------------------
// Kernel 3: aux_loss = E * sum_e (imp_e / T) * (load_e / T)
// ---------------------------------------------------------------------------
__global__ void aux_kernel(float* __restrict__ out)
{
    __shared__ float s[E_NUM];
    int t = threadIdx.x;
    s[t] = g_imp[t] * g_load[t];
    __syncthreads();
    if (t == 0) {
        float a = 0.f;
        for (int e = 0; e < E_NUM; e++) a += s[e];
        out[4 * T_TOK] = (float)E_NUM * a / ((float)T_TOK * (float)T_TOK);
    }
}

// ---------------------------------------------------------------------------
extern "C" void kernel_launch(void* const* d_in, const int* in_sizes, int n_in,
                              void* d_out, int out_size)
{
    const float* x      = (const float*)d_in[0];
    const float* rc     = (const float*)d_in[1];
    const float* gate_w = (const float*)d_in[2];
    const float* ctx_w  = (const float*)d_in[3];
    float* out = (float*)d_out;

    ctx_kernel   <<<64, 256>>>(rc, ctx_w);
    router_kernel<<<128, 256>>>(x, gate_w, out);
    aux_kernel   <<<1, E_NUM>>>(out);
}

// round 3
// speedup vs baseline: 1.4053x; 1.4053x over previous
#include <cuda_runtime.h>
#include <math.h>

#define T_TOK 16384
#define C_DIM 2048
#define E_NUM 64

__device__ float g_ctx[4 * C_DIM];      // (4, 2048)  context projection
__device__ float g_imp[E_NUM];          // sum of probs per expert
__device__ float g_load[E_NUM];         // top-k pick counts per expert

// packed f32x2 FMA: d = a * b + d  (two IEEE fp32 FMAs, one instruction)
__device__ __forceinline__ void ffma2(unsigned long long& d,
                                      unsigned long long a,
                                      unsigned long long b)
{
    asm("fma.rn.f32x2 %0, %1, %2, %0;" : "+l"(d) : "l"(a), "l"(b));
}
__device__ __forceinline__ unsigned long long pack2(float v)
{
    unsigned long long r;
    unsigned int u = __float_as_uint(v);
    asm("mov.b64 %0, {%1, %1};" : "=l"(r) : "r"(u));
    return r;
}

// ---------------------------------------------------------------------------
// Kernel 1: ctx[b][c] = sum_k rc[b][k] * ctx_w[c][k]
// One warp per column c (2048 warps), float4 streaming of ctx_w (16 MB).
// Also zeroes the global accumulators (runs first every replay).
// ---------------------------------------------------------------------------
__global__ void __launch_bounds__(256) ctx_kernel(const float* __restrict__ rc,
                                                  const float* __restrict__ ctx_w)
{
    if (blockIdx.x == 0 && threadIdx.x < 2 * E_NUM) {
        if (threadIdx.x < E_NUM) g_imp[threadIdx.x] = 0.f;
        else                     g_load[threadIdx.x - E_NUM] = 0.f;
    }
    const int c    = blockIdx.x * 8 + (threadIdx.x >> 5);   // 0..2047
    const int lane = threadIdx.x & 31;

    const float4* w4  = (const float4*)(ctx_w + (size_t)c * C_DIM) + lane;
    const float4* rc0 = (const float4*)(rc)                + lane;
    const float4* rc1 = (const float4*)(rc +     C_DIM)    + lane;
    const float4* rc2 = (const float4*)(rc + 2 * C_DIM)    + lane;
    const float4* rc3 = (const float4*)(rc + 3 * C_DIM)    + lane;

    float a0 = 0.f, a1 = 0.f, a2 = 0.f, a3 = 0.f;
    #pragma unroll
    for (int j = 0; j < 16; j++) {                // 16 float4 per lane
        float4 wv = w4 [j * 32];
        float4 r0 = rc0[j * 32];
        float4 r1 = rc1[j * 32];
        float4 r2 = rc2[j * 32];
        float4 r3 = rc3[j * 32];
        a0 = fmaf(wv.x, r0.x, fmaf(wv.y, r0.y, fmaf(wv.z, r0.z, fmaf(wv.w, r0.w, a0))));
        a1 = fmaf(wv.x, r1.x, fmaf(wv.y, r1.y, fmaf(wv.z, r1.z, fmaf(wv.w, r1.w, a1))));
        a2 = fmaf(wv.x, r2.x, fmaf(wv.y, r2.y, fmaf(wv.z, r2.z, fmaf(wv.w, r2.w, a2))));
        a3 = fmaf(wv.x, r3.x, fmaf(wv.y, r3.y, fmaf(wv.z, r3.z, fmaf(wv.w, r3.w, a3))));
    }
    #pragma unroll
    for (int o = 16; o; o >>= 1) {
        a0 += __shfl_down_sync(0xffffffffu, a0, o);
        a1 += __shfl_down_sync(0xffffffffu, a1, o);
        a2 += __shfl_down_sync(0xffffffffu, a2, o);
        a3 += __shfl_down_sync(0xffffffffu, a3, o);
    }
    if (lane == 0) {
        g_ctx[c]             = a0;
        g_ctx[C_DIM + c]     = a1;
        g_ctx[2 * C_DIM + c] = a2;
        g_ctx[3 * C_DIM + c] = a3;
    }
}

// ---------------------------------------------------------------------------
// Kernel 2: main GEMM (logits = (x + ctx) @ gate_w.T) + fused router
// epilogue (top-2, softmax weights, importance/load accumulation).
// ctx added at x-tile load time (matches reference rounding exactly).
// Block: 256 threads, BM=128 tokens, all 64 experts, BK=16.
// Thread micro-tile: 4 tokens x 8 experts, accumulated as f32x2 pairs
// along the expert dim via fma.rn.f32x2 (2 FMAs per fma-pipe issue).
// ---------------------------------------------------------------------------
__global__ void __launch_bounds__(256, 1) router_kernel(const float* __restrict__ x,
                                                        const float* __restrict__ gate_w,
                                                        float* __restrict__ out)
{
    __shared__ float xs[16 * 128];     // xs[k][token]  (k-major)
    __shared__ float gs[16 * 64];      // gs[k][expert]
    __shared__ float sLog[128 * 65];   // padded logits rows
    __shared__ float sImp[E_NUM];
    __shared__ int   sLoad[E_NUM];

    const int tid    = threadIdx.x;
    const int token0 = blockIdx.x * 128;
    const int batch  = token0 >> 12;   // 128 | 4096, so one batch per block

    // loader mapping: tid -> (row lt, k-quad lk)
    const int lt = tid >> 2;          // 0..63
    const int lk = (tid & 3) << 2;    // 0,4,8,12
    const float4* xpA = (const float4*)(x      + (size_t)(token0 + lt)      * C_DIM + lk);
    const float4* xpB = (const float4*)(x      + (size_t)(token0 + lt + 64) * C_DIM + lk);
    const float4* gp  = (const float4*)(gate_w + (size_t)lt                 * C_DIM + lk);
    const float4* cp  = (const float4*)(g_ctx  + (size_t)batch              * C_DIM + lk);

    // compute mapping: tid -> (token base ti, expert base ej)
    const int ti = (tid & 31) << 2;   // 0..124 step 4
    const int ej = (tid >> 5) << 3;   // 0..56  step 8

    unsigned long long acc2[4][4];    // [token][expert-pair]
    #pragma unroll
    for (int a = 0; a < 4; a++)
        #pragma unroll
        for (int b = 0; b < 4; b++) acc2[a][b] = 0ull;

    float4 ra = *xpA, rb = *xpB, rg = *gp, rc = *cp;

    for (int kc = 0; kc < 128; kc++) {
        // store current chunk (transposed to k-major), ctx fused into x
        #pragma unroll
        for (int i = 0; i < 4; i++) {
            float cv = ((const float*)&rc)[i];
            xs[(lk + i) * 128 + lt]      = ((const float*)&ra)[i] + cv;
            xs[(lk + i) * 128 + lt + 64] = ((const float*)&rb)[i] + cv;
            gs[(lk + i) * 64 + lt]       = ((const float*)&rg)[i];
        }
        __syncthreads();
        // prefetch next chunk (LDG overlaps the FMA block below)
        if (kc < 127) {
            ra = xpA[(kc + 1) * 4];
            rb = xpB[(kc + 1) * 4];
            rg = gp [(kc + 1) * 4];
            rc = cp [(kc + 1) * 4];
        }
        #pragma unroll
        for (int kk = 0; kk < 16; kk++) {
            float4 xv = *(const float4*)&xs[kk * 128 + ti];
            // experts as packed pairs: 2 x LDS.128 = 4 x f32x2 operands
            ulonglong2 gA = *(const ulonglong2*)&gs[kk * 64 + ej];       // e0e1, e2e3
            ulonglong2 gB = *(const ulonglong2*)&gs[kk * 64 + ej + 4];   // e4e5, e6e7
            unsigned long long xp[4] = {pack2(xv.x), pack2(xv.y), pack2(xv.z), pack2(xv.w)};
            #pragma unroll
            for (int a = 0; a < 4; a++) {
                ffma2(acc2[a][0], xp[a], gA.x);
                ffma2(acc2[a][1], xp[a], gA.y);
                ffma2(acc2[a][2], xp[a], gB.x);
                ffma2(acc2[a][3], xp[a], gB.y);
            }
        }
        __syncthreads();
    }

    // spill logits to smem (padded rows: stride 65 avoids bank conflicts)
    if (tid < E_NUM) { sImp[tid] = 0.f; sLoad[tid] = 0; }
    #pragma unroll
    for (int a = 0; a < 4; a++)
        #pragma unroll
        for (int b = 0; b < 4; b++) {
            unsigned int lo, hi;
            asm("mov.b64 {%0, %1}, %2;" : "=r"(lo), "=r"(hi) : "l"(acc2[a][b]));
            sLog[(ti + a) * 65 + ej + 2 * b]     = __uint_as_float(lo);
            sLog[(ti + a) * 65 + ej + 2 * b + 1] = __uint_as_float(hi);
        }
    __syncthreads();

    // -------- fused epilogue: one thread per token --------
    if (tid < 128) {
        const int tok = token0 + tid;
        float* row = &sLog[tid * 65];

        // top-2 with jax tie-break (strict >, lowest index wins ties)
        float v0 = -1e30f, v1 = -1e30f;
        int   i0 = 0, i1 = 0;
        for (int e = 0; e < E_NUM; e++) {
            float l = row[e];
            if (l > v0)      { v1 = v0; i1 = i0; v0 = l; i0 = e; }
            else if (l > v1) { v1 = l; i1 = e; }
        }
        // full softmax (stable at max v0); cache exp in row
        float sum = 0.f;
        for (int e = 0; e < E_NUM; e++) {
            float p = expf(row[e] - v0);
            row[e] = p;
            sum += p;
        }
        float inv = 1.0f / sum;
        // importance accumulation, lane-staggered to avoid same-address atomics
        int lane = tid & 31;
        for (int e = 0; e < E_NUM; e++) {
            int ee = (e + lane) & 63;
            atomicAdd(&sImp[ee], row[ee] * inv);
        }
        atomicAdd(&sLoad[i0], 1);
        atomicAdd(&sLoad[i1], 1);

        // top-2 softmax weights
        float e1 = expf(v1 - v0);
        float w0 = 1.0f / (1.0f + e1);
        out[(size_t)tok * 2 + 0] = (float)i0;
        out[(size_t)tok * 2 + 1] = (float)i1;
        out[2 * T_TOK + (size_t)tok * 2 + 0] = w0;
        out[2 * T_TOK + (size_t)tok * 2 + 1] = e1 * w0;   // = 1 - w0
    }
    __syncthreads();
    if (tid < E_NUM) {
        atomicAdd(&g_imp[tid],  sImp[tid]);
        atomicAdd(&g_load[tid], (float)sLoad[tid]);
    }
}

// ---------------------------------------------------------------------------
// Kernel 3: aux_loss = E * sum_e (imp_e / T) * (load_e / T)
// ---------------------------------------------------------------------------
__global__ void aux_kernel(float* __restrict__ out)
{
    __shared__ float s[E_NUM];
    int t = threadIdx.x;
    s[t] = g_imp[t] * g_load[t];
    __syncthreads();
    if (t == 0) {
        float a = 0.f;
        for (int e = 0; e < E_NUM; e++) a += s[e];
        out[4 * T_TOK] = (float)E_NUM * a / ((float)T_TOK * (float)T_TOK);
    }
}

// ---------------------------------------------------------------------------
extern "C" void kernel_launch(void* const* d_in, const int* in_sizes, int n_in,
                              void* d_out, int out_size)
{
    const float* x      = (const float*)d_in[0];
    const float* rc     = (const float*)d_in[1];
    const float* gate_w = (const float*)d_in[2];
    const float* ctx_w  = (const float*)d_in[3];
    float* out = (float*)d_out;

    ctx_kernel   <<<256, 256>>>(rc, ctx_w);
    router_kernel<<<128, 256>>>(x, gate_w, out);
    aux_kernel   <<<1, E_NUM>>>(out);
}